// round 2
// baseline (speedup 1.0000x reference)
#include <cuda_runtime.h>
#include <cuda_bf16.h>
#include <math.h>

#define NN 32768
#define NE 65536
#define HID 64
#define FC1 128

// ---------------- scratch (device globals; no allocation) ----------------
__device__ float g_sum1[NN * HID];   // layer1 scatter sum
__device__ float g_sum2[NN * HID];   // layer2 scatter sum
__device__ float g_cnt [NN];         // per-node edge count (same for both layers)
__device__ float g_h1  [NN * HID];   // layer1 node output
__device__ float g_h2e [NE * HID];   // relu(edge_attr @ W2a + b2a) per edge
__device__ float g_h2  [NN * HID];   // layer2 node output

__device__ __forceinline__ float elu1(float v) {
    return v > 0.f ? v : expm1f(v);
}

// ---------------- zero scratch ----------------
__global__ void zero_kernel() {
    int i = blockIdx.x * blockDim.x + threadIdx.x;        // exactly NN*HID threads
    g_sum1[i] = 0.f;
    g_sum2[i] = 0.f;
    if (i < NN) g_cnt[i] = 0.f;
}

// ---------------- layer 1 edge stage (+ precompute h2e, counts) ----------------
// one block (64 threads) per edge
__global__ __launch_bounds__(64) void edge1_kernel(
    const float* __restrict__ x, const int* __restrict__ ei,
    const float* __restrict__ ea_g,
    const float* __restrict__ W1a, const float* __restrict__ b1a,
    const float* __restrict__ W1b, const float* __restrict__ b1b,
    const float* __restrict__ W2a, const float* __restrict__ b2a)
{
    __shared__ float ea[3], xs[3], h1e[64];
    int e = blockIdx.x;
    int t = threadIdx.x;
    int src = ei[e];
    int dst = ei[NE + e];
    if (t < 3) {
        ea[t] = ea_g[e * 3 + t];
        xs[t] = x[src * 3 + t];
    }
    __syncthreads();
    float a0 = ea[0], a1 = ea[1], a2 = ea[2];
    // edge MLP hidden (layer1) and layer2 edge-MLP hidden
    float h = b1a[t] + a0 * W1a[t] + a1 * W1a[64 + t] + a2 * W1a[128 + t];
    h1e[t] = fmaxf(h, 0.f);
    float h2 = b2a[t] + a0 * W2a[t] + a1 * W2a[64 + t] + a2 * W2a[128 + t];
    g_h2e[e * 64 + t] = fmaxf(h2, 0.f);
    __syncthreads();

    // We1[i][t] = b1b[i*64+t] + sum_k h1e[k] * W1b[k*192 + i*64 + t]
    float msg = 0.f;
    #pragma unroll
    for (int i = 0; i < 3; ++i) {
        float we = b1b[i * 64 + t];
        const float* wp = W1b + i * 64 + t;
        #pragma unroll 8
        for (int k = 0; k < 64; ++k)
            we = fmaf(h1e[k], __ldg(wp + k * 192), we);
        msg = fmaf(xs[i], we, msg);
    }
    atomicAdd(&g_sum1[dst * 64 + t], msg);
    if (t == 0) atomicAdd(&g_cnt[dst], 1.f);
}

// ---------------- layer 1 node combine ----------------
__global__ void node1_kernel(const float* __restrict__ x,
                             const float* __restrict__ root1,
                             const float* __restrict__ bias1)
{
    int idx = blockIdx.x * blockDim.x + threadIdx.x;   // NN*64 threads
    int n = idx >> 6, o = idx & 63;
    float c = fmaxf(g_cnt[n], 1.f);
    float agg = g_sum1[idx] / c;
    float v = agg + bias1[o]
            + x[n * 3 + 0] * root1[o]
            + x[n * 3 + 1] * root1[64 + o]
            + x[n * 3 + 2] * root1[128 + o];
    g_h1[idx] = elu1(v);
}

// ---------------- layer 2 edge stage: the big bilinear GEMM ----------------
// msg2[e,o] = sum_{k,i} u[e,k]*v[e,i]*W2b[k*4096 + i*64 + o] + sum_i v[e,i]*b2b[i*64+o]
// Tile: 64 edges/block, 128 threads, each thread: 4 edges x 8 outputs.
#define TE 64
__global__ __launch_bounds__(128) void edge2_kernel(
    const int* __restrict__ ei,
    const float* __restrict__ W2b, const float* __restrict__ b2b)
{
    __shared__ float u_t[64][TE];   // [k][e]
    __shared__ float v_t[64][TE];   // [i][e]
    __shared__ int   src_s[TE];
    __shared__ int   dst_s[TE];

    int e0 = blockIdx.x * TE;
    int t  = threadIdx.x;

    if (t < TE) {
        src_s[t] = ei[e0 + t];
        dst_s[t] = ei[NE + e0 + t];
    }
    __syncthreads();

    // load u (h2e tile, transposed) and v (gathered h1[src], transposed)
    for (int idx = t; idx < TE * 64; idx += 128) {
        int e = idx >> 6, c = idx & 63;
        u_t[c][e] = g_h2e[(e0 + e) * 64 + c];
        v_t[c][e] = g_h1[src_s[e] * 64 + c];
    }
    __syncthreads();

    int tx = t & 7;          // output group: o = 8*tx .. 8*tx+7
    int ty = t >> 3;         // edge group:   e = 4*ty .. 4*ty+3
    int ob = tx * 8, eb = ty * 4;

    float acc[4][8];
    #pragma unroll
    for (int e = 0; e < 4; ++e)
        #pragma unroll
        for (int j = 0; j < 8; ++j) acc[e][j] = 0.f;

    for (int k = 0; k < 64; ++k) {
        float4 uk = *reinterpret_cast<const float4*>(&u_t[k][eb]);
        const float* wp = W2b + k * 4096 + ob;
        #pragma unroll 8
        for (int i = 0; i < 64; ++i) {
            float4 vi = *reinterpret_cast<const float4*>(&v_t[i][eb]);
            float4 wa = __ldg(reinterpret_cast<const float4*>(wp));
            float4 wb = __ldg(reinterpret_cast<const float4*>(wp + 4));
            wp += 64;
            float p[4] = {uk.x * vi.x, uk.y * vi.y, uk.z * vi.z, uk.w * vi.w};
            float w[8] = {wa.x, wa.y, wa.z, wa.w, wb.x, wb.y, wb.z, wb.w};
            #pragma unroll
            for (int e = 0; e < 4; ++e)
                #pragma unroll
                for (int j = 0; j < 8; ++j)
                    acc[e][j] = fmaf(p[e], w[j], acc[e][j]);
        }
    }
    // bias term: pseudo-k with u = 1
    {
        const float* wp = b2b + ob;
        #pragma unroll 8
        for (int i = 0; i < 64; ++i) {
            float4 vi = *reinterpret_cast<const float4*>(&v_t[i][eb]);
            float4 wa = __ldg(reinterpret_cast<const float4*>(wp));
            float4 wb = __ldg(reinterpret_cast<const float4*>(wp + 4));
            wp += 64;
            float p[4] = {vi.x, vi.y, vi.z, vi.w};
            float w[8] = {wa.x, wa.y, wa.z, wa.w, wb.x, wb.y, wb.z, wb.w};
            #pragma unroll
            for (int e = 0; e < 4; ++e)
                #pragma unroll
                for (int j = 0; j < 8; ++j)
                    acc[e][j] = fmaf(p[e], w[j], acc[e][j]);
        }
    }

    // scatter-add into g_sum2
    #pragma unroll
    for (int e = 0; e < 4; ++e) {
        int d = dst_s[eb + e];
        float* outp = &g_sum2[d * 64 + ob];
        #pragma unroll
        for (int j = 0; j < 8; ++j)
            atomicAdd(outp + j, acc[e][j]);
    }
}

// ---------------- layer 2 node combine ----------------
__global__ __launch_bounds__(256) void node2_kernel(
    const float* __restrict__ root2, const float* __restrict__ bias2)
{
    __shared__ float hs[4][64];
    int nb = blockIdx.x * 4;
    int t = threadIdx.x;
    int ln = t >> 6, o = t & 63;
    hs[ln][o] = g_h1[(nb + ln) * 64 + o];
    __syncthreads();
    int n = nb + ln;
    float acc = bias2[o];
    #pragma unroll 8
    for (int i = 0; i < 64; ++i)
        acc = fmaf(hs[ln][i], __ldg(&root2[i * 64 + o]), acc);
    float c = fmaxf(g_cnt[n], 1.f);
    acc += g_sum2[n * 64 + o] / c;
    g_h2[n * 64 + o] = elu1(acc);
}

// ---------------- final FC ----------------
__global__ __launch_bounds__(256) void fc_kernel(
    const float* __restrict__ Wf, const float* __restrict__ bf,
    float* __restrict__ out)
{
    __shared__ float hs[2][64];
    int nb = blockIdx.x * 2;
    int t = threadIdx.x;
    int ln = t >> 7, o = t & 127;
    if (o < 64) hs[ln][o] = g_h2[(nb + ln) * 64 + o];
    __syncthreads();
    float acc = bf[o];
    #pragma unroll 8
    for (int i = 0; i < 64; ++i)
        acc = fmaf(hs[ln][i], __ldg(&Wf[i * 128 + o]), acc);
    out[(nb + ln) * 128 + o] = elu1(acc);
}

// ---------------- launch ----------------
extern "C" void kernel_launch(void* const* d_in, const int* in_sizes, int n_in,
                              void* d_out, int out_size)
{
    const float* x     = (const float*)d_in[0];
    const int*   ei    = (const int*)d_in[1];      // JAX default: int32, not int64!
    const float* ea    = (const float*)d_in[2];
    const float* W1a   = (const float*)d_in[3];
    const float* b1a   = (const float*)d_in[4];
    const float* W1b   = (const float*)d_in[5];
    const float* b1b   = (const float*)d_in[6];
    const float* root1 = (const float*)d_in[7];
    const float* bias1 = (const float*)d_in[8];
    const float* W2a   = (const float*)d_in[9];
    const float* b2a   = (const float*)d_in[10];
    const float* W2b   = (const float*)d_in[11];
    const float* b2b   = (const float*)d_in[12];
    const float* root2 = (const float*)d_in[13];
    const float* bias2 = (const float*)d_in[14];
    const float* Wf    = (const float*)d_in[15];
    const float* bf    = (const float*)d_in[16];
    float*       out   = (float*)d_out;

    zero_kernel <<<NN * HID / 256, 256>>>();
    edge1_kernel<<<NE, 64>>>(x, ei, ea, W1a, b1a, W1b, b1b, W2a, b2a);
    node1_kernel<<<NN * HID / 256, 256>>>(x, root1, bias1);
    edge2_kernel<<<NE / TE, 128>>>(ei, W2b, b2b);
    node2_kernel<<<NN / 4, 256>>>(root2, bias2);
    fc_kernel   <<<NN / 2, 256>>>(Wf, bf, out);
}

// round 4
// speedup vs baseline: 3.3715x; 3.3715x over previous
#include <cuda_runtime.h>
#include <math.h>
#include <stdint.h>

#define NN 32768
#define NE 65536

// ---------------- device scratch ----------------
__device__ float g_sum1[NN * 64];
__device__ float g_sum2[NN * 64];
__device__ float g_cnt [NN];
__device__ float g_h1  [NN * 64];
__device__ float g_h2  [NN * 64];
__device__ float g_he1 [NE * 64];    // relu(ea@W1a+b1a)
__device__ float g_he2 [NE * 64];    // relu(ea@W2a+b2a)
__device__ float g_Bt1 [4  * 4096];  // layer1 B chunks [c][k][n], tf32-rounded
__device__ float g_Bt2 [65 * 4096];  // layer2 B chunks [c][i][n], tf32-rounded

__device__ __forceinline__ float elu1(float v) { return v > 0.f ? v : expm1f(v); }

__device__ __forceinline__ float tf32r(float f) {
    uint32_t r;
    asm("cvt.rna.tf32.f32 %0, %1;" : "=r"(r) : "f"(f));
    return __uint_as_float(r);
}

__device__ __forceinline__ void mma8(float* c, const uint32_t* a, uint32_t b0, uint32_t b1) {
    asm volatile(
        "mma.sync.aligned.m16n8k8.row.col.f32.tf32.tf32.f32 "
        "{%0,%1,%2,%3}, {%4,%5,%6,%7}, {%8,%9}, {%0,%1,%2,%3};"
        : "+f"(c[0]), "+f"(c[1]), "+f"(c[2]), "+f"(c[3])
        : "r"(a[0]), "r"(a[1]), "r"(a[2]), "r"(a[3]), "r"(b0), "r"(b1));
}

// ---------------- zero scratch ----------------
__global__ void zero_kernel() {
    int i = blockIdx.x * blockDim.x + threadIdx.x;   // NN*64 threads
    g_sum1[i] = 0.f;
    g_sum2[i] = 0.f;
    if (i < NN) g_cnt[i] = 0.f;
}

// ---------------- per-edge counts ----------------
__global__ void cnt_kernel(const int* __restrict__ ei) {
    int e = blockIdx.x * blockDim.x + threadIdx.x;   // NE threads
    atomicAdd(&g_cnt[ei[NE + e]], 1.f);
}

// ---------------- edge-MLP hiddens (both layers) ----------------
__global__ void he_kernel(const float* __restrict__ ea,
                          const float* __restrict__ W1a, const float* __restrict__ b1a,
                          const float* __restrict__ W2a, const float* __restrict__ b2a)
{
    int idx = blockIdx.x * blockDim.x + threadIdx.x;  // NE*64 threads
    int e = idx >> 6, t = idx & 63;
    float a0 = __ldg(&ea[e * 3]), a1 = __ldg(&ea[e * 3 + 1]), a2 = __ldg(&ea[e * 3 + 2]);
    float h1 = b1a[t] + a0 * W1a[t] + a1 * W1a[64 + t] + a2 * W1a[128 + t];
    float h2 = b2a[t] + a0 * W2a[t] + a1 * W2a[64 + t] + a2 * W2a[128 + t];
    g_he1[idx] = fmaxf(h1, 0.f);
    g_he2[idx] = fmaxf(h2, 0.f);
}

// ---------------- B-chunk prep (transposed, tf32-rounded) ----------------
// layer2: c<64:  Bt2[c][i][n] = W2b[c*4096 + i*64 + n]   (outer = k)
//         c==64: Bt2[64][i][n] = b2b[i*64 + n]           (bias step)
__global__ void btprep2_kernel(const float* __restrict__ W2b, const float* __restrict__ b2b) {
    int idx = blockIdx.x * blockDim.x + threadIdx.x;   // 65*4096 threads
    int c = idx >> 12, r = idx & 4095;
    float v = (c < 64) ? W2b[c * 4096 + r] : b2b[r];
    g_Bt2[idx] = tf32r(v);
}
// layer1: c<3:  Bt1[c][k][n] = W1b[k*192 + c*64 + n]     (outer = i, inner = k)
//         c==3: Bt1[3][k][n] = (k<3) ? b1b[k*64+n] : 0   (bias step)
__global__ void btprep1_kernel(const float* __restrict__ W1b, const float* __restrict__ b1b) {
    int idx = blockIdx.x * blockDim.x + threadIdx.x;   // 4*4096 threads
    int c = idx >> 12, r = idx & 4095, k = r >> 6, n = r & 63;
    float v;
    if (c < 3) v = W1b[k * 192 + c * 64 + n];
    else       v = (k < 3) ? b1b[k * 64 + n] : 0.f;
    g_Bt1[idx] = tf32r(v);
}

// ---------------- bilinear message GEMM via mma.sync tf32 ----------------
// D[m=edge 0..127][n=0..63] = sum over outer steps s of u[m,s] * (v[m,:] . B_s[:,n])
// LAYER2: u = he2[e] (+1 bias), v = h1[src], S = 65 outer x 64 inner
// LAYER1: u = x[src] (+1 bias), v = he1[e] (bias inner = x), S = 4 outer
template<int LAYER>
__global__ __launch_bounds__(256) void bilinear_kernel(const int* __restrict__ ei,
                                                       const float* __restrict__ x)
{
    constexpr int S     = (LAYER == 1) ? 4 : 65;
    constexpr int JLAST = (LAYER == 1) ? 1 : 8;
    const float* Bt   = (LAYER == 1) ? g_Bt1  : g_Bt2;
    float*       osum = (LAYER == 1) ? g_sum1 : g_sum2;

    extern __shared__ float sm[];
    float* U  = sm;                  // [128][68]
    float* V  = U  + 128 * 68;       // [128][68]
    float* VB = V  + 128 * 68;       // [128][12]
    float* Bs = VB + 128 * 12;       // [2][64*68]
    int*  srcs = (int*)(Bs + 2 * 64 * 68);   // [128]
    int*  dsts = srcs + 128;                  // [128]

    int t  = threadIdx.x;
    int e0 = blockIdx.x * 128;
    if (t < 128) { srcs[t] = ei[e0 + t]; dsts[t] = ei[NE + e0 + t]; }
    __syncthreads();

    // load V (and U for layer2), tf32-rounded
    for (int idx = t; idx < 128 * 16; idx += 256) {
        int m = idx >> 4, q4 = idx & 15;
        const float* vsrc = (LAYER == 1) ? (g_he1 + (e0 + m) * 64) : (g_h1 + srcs[m] * 64);
        float4 vv = __ldg((const float4*)vsrc + q4);
        vv.x = tf32r(vv.x); vv.y = tf32r(vv.y); vv.z = tf32r(vv.z); vv.w = tf32r(vv.w);
        *(float4*)(V + m * 68 + q4 * 4) = vv;
        if (LAYER == 2) {
            float4 uu = __ldg((const float4*)(g_he2 + (e0 + m) * 64) + q4);
            uu.x = tf32r(uu.x); uu.y = tf32r(uu.y); uu.z = tf32r(uu.z); uu.w = tf32r(uu.w);
            *(float4*)(U + m * 68 + q4 * 4) = uu;
        }
    }
    if (t < 128) {
        if (LAYER == 2) {
            U[t * 68 + 64] = 1.f;
        } else {
            const float* xp = x + srcs[t] * 3;
            float x0 = tf32r(__ldg(xp)), x1 = tf32r(__ldg(xp + 1)), x2 = tf32r(__ldg(xp + 2));
            U[t * 68 + 0] = x0; U[t * 68 + 1] = x1; U[t * 68 + 2] = x2; U[t * 68 + 3] = 1.f;
            VB[t * 12 + 0] = x0; VB[t * 12 + 1] = x1; VB[t * 12 + 2] = x2;
            #pragma unroll
            for (int k = 3; k < 8; ++k) VB[t * 12 + k] = 0.f;
        }
    }
    // prefetch B chunk 0 into buffer 0
    {
        const float4* gp = (const float4*)Bt + t * 4;
        #pragma unroll
        for (int j = 0; j < 4; ++j) {
            int fi = t * 4 + j, row = fi >> 4, c4 = fi & 15;
            *(float4*)(Bs + row * 68 + c4 * 4) = __ldg(gp + j);
        }
    }
    __syncthreads();

    int lane = t & 31, wid = t >> 5;
    int g = lane >> 2, q = lane & 3;
    int wm = wid >> 1, wn = wid & 1;
    int mb = wm * 32;

    float cacc[2][4][4];
    #pragma unroll
    for (int a = 0; a < 2; ++a)
        #pragma unroll
        for (int b = 0; b < 4; ++b)
            #pragma unroll
            for (int cx = 0; cx < 4; ++cx) cacc[a][b][cx] = 0.f;

    for (int s = 0; s < S; ++s) {
        float4 pf[4];
        if (s + 1 < S) {
            const float4* gp = (const float4*)(Bt + (s + 1) * 4096) + t * 4;
            #pragma unroll
            for (int j = 0; j < 4; ++j) pf[j] = __ldg(gp + j);
        }
        const float* Vc = V;
        int vst = 68;
        int jmax = (s == S - 1) ? JLAST : 8;
        if (LAYER == 1 && s == S - 1) { Vc = VB; vst = 12; }

        float us[4];
        #pragma unroll
        for (int r = 0; r < 4; ++r) us[r] = U[(mb + r * 8 + g) * 68 + s];

        const float* B0 = Bs + (s & 1) * (64 * 68);
        for (int j = 0; j < jmax; ++j) {
            int i0 = j * 8 + q, i1 = i0 + 4;
            float v0[4], v1[4];
            #pragma unroll
            for (int r = 0; r < 4; ++r) {
                const float* vp = Vc + (mb + r * 8 + g) * vst;
                v0[r] = vp[i0]; v1[r] = vp[i1];
            }
            uint32_t a[2][4];
            #pragma unroll
            for (int mt = 0; mt < 2; ++mt) {
                a[mt][0] = __float_as_uint(us[mt * 2]     * v0[mt * 2]);
                a[mt][1] = __float_as_uint(us[mt * 2 + 1] * v0[mt * 2 + 1]);
                a[mt][2] = __float_as_uint(us[mt * 2]     * v1[mt * 2]);
                a[mt][3] = __float_as_uint(us[mt * 2 + 1] * v1[mt * 2 + 1]);
            }
            #pragma unroll
            for (int nt = 0; nt < 4; ++nt) {
                int n0 = wn * 32 + nt * 8 + g;
                uint32_t b0 = __float_as_uint(B0[i0 * 68 + n0]);
                uint32_t b1 = __float_as_uint(B0[i1 * 68 + n0]);
                mma8(cacc[0][nt], a[0], b0, b1);
                mma8(cacc[1][nt], a[1], b0, b1);
            }
        }
        if (s + 1 < S) {
            float* Bn = Bs + ((s + 1) & 1) * (64 * 68);
            #pragma unroll
            for (int j = 0; j < 4; ++j) {
                int fi = t * 4 + j, row = fi >> 4, c4 = fi & 15;
                *(float4*)(Bn + row * 68 + c4 * 4) = pf[j];
            }
        }
        __syncthreads();
    }

    // epilogue: scatter-add C fragments
    #pragma unroll
    for (int mt = 0; mt < 2; ++mt) {
        #pragma unroll
        for (int half = 0; half < 2; ++half) {
            int m = mb + mt * 16 + half * 8 + g;
            float* op = osum + dsts[m] * 64 + wn * 32 + 2 * q;
            #pragma unroll
            for (int nt = 0; nt < 4; ++nt) {
                atomicAdd(op + nt * 8,     cacc[mt][nt][half * 2 + 0]);
                atomicAdd(op + nt * 8 + 1, cacc[mt][nt][half * 2 + 1]);
            }
        }
    }
}

// ---------------- layer 1 node combine ----------------
__global__ void node1_kernel(const float* __restrict__ x,
                             const float* __restrict__ root1,
                             const float* __restrict__ bias1)
{
    int idx = blockIdx.x * blockDim.x + threadIdx.x;   // NN*64 threads
    int n = idx >> 6, o = idx & 63;
    float c = fmaxf(g_cnt[n], 1.f);
    float v = g_sum1[idx] / c + bias1[o]
            + x[n * 3 + 0] * root1[o]
            + x[n * 3 + 1] * root1[64 + o]
            + x[n * 3 + 2] * root1[128 + o];
    g_h1[idx] = elu1(v);
}

// ---------------- layer 2 node combine ----------------
__global__ __launch_bounds__(256) void node2_kernel(
    const float* __restrict__ root2, const float* __restrict__ bias2)
{
    __shared__ float hs[4][64];
    int nb = blockIdx.x * 4;
    int t = threadIdx.x;
    int ln = t >> 6, o = t & 63;
    hs[ln][o] = g_h1[(nb + ln) * 64 + o];
    __syncthreads();
    int n = nb + ln;
    float acc = bias2[o];
    #pragma unroll 8
    for (int i = 0; i < 64; ++i)
        acc = fmaf(hs[ln][i], __ldg(&root2[i * 64 + o]), acc);
    float c = fmaxf(g_cnt[n], 1.f);
    acc += g_sum2[n * 64 + o] / c;
    g_h2[n * 64 + o] = elu1(acc);
}

// ---------------- final FC ----------------
__global__ __launch_bounds__(256) void fc_kernel(
    const float* __restrict__ Wf, const float* __restrict__ bf,
    float* __restrict__ out)
{
    __shared__ float hs[2][64];
    int nb = blockIdx.x * 2;
    int t = threadIdx.x;
    int ln = t >> 7, o = t & 127;
    if (o < 64) hs[ln][o] = g_h2[(nb + ln) * 64 + o];
    __syncthreads();
    float acc = bf[o];
    #pragma unroll 8
    for (int i = 0; i < 64; ++i)
        acc = fmaf(hs[ln][i], __ldg(&Wf[i * 128 + o]), acc);
    out[(nb + ln) * 128 + o] = elu1(acc);
}

// ---------------- launch ----------------
#define SM_BYTES ((128*68*2 + 128*12 + 2*64*68) * 4 + 256 * 4)

extern "C" void kernel_launch(void* const* d_in, const int* in_sizes, int n_in,
                              void* d_out, int out_size)
{
    const float* x     = (const float*)d_in[0];
    const int*   ei    = (const int*)d_in[1];
    const float* ea    = (const float*)d_in[2];
    const float* W1a   = (const float*)d_in[3];
    const float* b1a   = (const float*)d_in[4];
    const float* W1b   = (const float*)d_in[5];
    const float* b1b   = (const float*)d_in[6];
    const float* root1 = (const float*)d_in[7];
    const float* bias1 = (const float*)d_in[8];
    const float* W2a   = (const float*)d_in[9];
    const float* b2a   = (const float*)d_in[10];
    const float* W2b   = (const float*)d_in[11];
    const float* b2b   = (const float*)d_in[12];
    const float* root2 = (const float*)d_in[13];
    const float* bias2 = (const float*)d_in[14];
    const float* Wf    = (const float*)d_in[15];
    const float* bf    = (const float*)d_in[16];
    float*       out   = (float*)d_out;

    static int attr_done = 0;
    if (!attr_done) {
        cudaFuncSetAttribute(bilinear_kernel<1>, cudaFuncAttributeMaxDynamicSharedMemorySize, SM_BYTES);
        cudaFuncSetAttribute(bilinear_kernel<2>, cudaFuncAttributeMaxDynamicSharedMemorySize, SM_BYTES);
        attr_done = 1;
    }

    zero_kernel   <<<NN * 64 / 256, 256>>>();
    cnt_kernel    <<<NE / 256, 256>>>(ei);
    he_kernel     <<<NE * 64 / 256, 256>>>(ea, W1a, b1a, W2a, b2a);
    btprep1_kernel<<<4  * 4096 / 256, 256>>>(W1b, b1b);
    btprep2_kernel<<<65 * 4096 / 256, 256>>>(W2b, b2b);
    bilinear_kernel<1><<<NE / 128, 256, SM_BYTES>>>(ei, x);
    node1_kernel  <<<NN * 64 / 256, 256>>>(x, root1, bias1);
    bilinear_kernel<2><<<NE / 128, 256, SM_BYTES>>>(ei, x);
    node2_kernel  <<<NN / 4, 256>>>(root2, bias2);
    fc_kernel     <<<NN / 2, 256>>>(Wf, bf, out);
}